// round 14
// baseline (speedup 1.0000x reference)
#include <cuda_runtime.h>
#include <cstdint>

#define NN 100000
#define NE 1600000
#define C  128

#define GEMM_BLOCKS  ((NN + 127) / 128)       // 782
#define EDGE4_BLOCKS ((NE / 4 + 255) / 256)   // 1563

#define SCAN_CHUNK 1024
#define NBLK_SCAN ((NN + SCAN_CHUNK - 1) / SCAN_CHUNK)   // 98

#define NCHUNK 4
#define CHUNK_BLKS 196                         // gemm blocks per chunk (last: 194)
#define CHUNK_NODES (CHUNK_BLKS * 128)         // 25088

// ---------------------------------------------------------------------------
// Scratch (device globals — no allocation allowed)
// ---------------------------------------------------------------------------
__device__ int   g_cnt [NN];
__device__ int   g_off [NN + 1];
__device__ int   g_bsum[SCAN_CHUNK];
__device__ int   g_csrc[NE];
__device__ float g_dinv[NN];
__device__ float g_h   [(size_t)NN * C];   // x@W1 (fp32)
__device__ float g_hn  [(size_t)NN * C];   // normalized hidden (fp32)
__device__ float g_agg2[(size_t)NN * C];   // stage-2 aggregate (tf32-rounded fp32)

__device__ __forceinline__ uint32_t f2tf32(float f) {
    uint32_t r; asm("cvt.rna.tf32.f32 %0, %1;" : "=r"(r) : "f"(f)); return r;
}

// ---------------------------------------------------------------------------
// CSR build pieces (side stream, overlapped with GEMM1)
// ---------------------------------------------------------------------------
__global__ void count_kernel(const int* __restrict__ dst) {
    int t = blockIdx.x * blockDim.x + threadIdx.x;
    if (t < NE / 4) {
        int4 d = reinterpret_cast<const int4*>(dst)[t];
        atomicAdd(&g_cnt[d.x], 1);
        atomicAdd(&g_cnt[d.y], 1);
        atomicAdd(&g_cnt[d.z], 1);
        atomicAdd(&g_cnt[d.w], 1);
    }
}

__global__ __launch_bounds__(SCAN_CHUNK)
void scan1_kernel() {
    const int tid = threadIdx.x, lane = tid & 31, wid = tid >> 5;
    int i = blockIdx.x * SCAN_CHUNK + tid;
    int v = (i < NN) ? g_cnt[i] : 0;
    int x = v;
#pragma unroll
    for (int off = 1; off < 32; off <<= 1) {
        int y = __shfl_up_sync(0xffffffffu, x, off);
        if (lane >= off) x += y;
    }
    __shared__ int ws[32];
    if (lane == 31) ws[wid] = x;
    __syncthreads();
    if (wid == 0) {
        int s = ws[lane];
        int t = s;
#pragma unroll
        for (int off = 1; off < 32; off <<= 1) {
            int y = __shfl_up_sync(0xffffffffu, t, off);
            if (lane >= off) t += y;
        }
        ws[lane] = t - s;
        if (lane == 31) g_bsum[blockIdx.x] = t;
    }
    __syncthreads();
    if (i < NN) g_off[i] = (x - v) + ws[wid];
}

__global__ __launch_bounds__(SCAN_CHUNK)
void scan3_kernel() {
    __shared__ int sb[128];
    const int tid = threadIdx.x;
    if (tid < 128) sb[tid] = (tid < NBLK_SCAN) ? g_bsum[tid] : 0;
    __syncthreads();
#pragma unroll
    for (int off = 1; off < 128; off <<= 1) {
        int t = 0;
        if (tid < 128 && tid >= off) t = sb[tid - off];
        __syncthreads();
        if (tid < 128) sb[tid] += t;
        __syncthreads();
    }
    const int boff = sb[blockIdx.x] - g_bsum[blockIdx.x];
    int i = blockIdx.x * SCAN_CHUNK + tid;
    if (i < NN) {
        g_off[i] += boff;
        g_dinv[i] = rsqrtf((float)g_cnt[i] + 1.0f);
        g_cnt[i] = 0;
    }
    if (i == 0) g_off[NN] = NE;
}

__global__ void fill_kernel(const int* __restrict__ src, const int* __restrict__ dst) {
    int t = blockIdx.x * blockDim.x + threadIdx.x;
    if (t < NE / 4) {
        int4 s = reinterpret_cast<const int4*>(src)[t];
        int4 d = reinterpret_cast<const int4*>(dst)[t];
        int p;
        p = atomicAdd(&g_cnt[d.x], 1); g_csrc[g_off[d.x] + p] = s.x;
        p = atomicAdd(&g_cnt[d.y], 1); g_csrc[g_off[d.y] + p] = s.y;
        p = atomicAdd(&g_cnt[d.z], 1); g_csrc[g_off[d.z] + p] = s.z;
        p = atomicAdd(&g_cnt[d.w], 1); g_csrc[g_off[d.w] + p] = s.w;
    }
}

// ---------------------------------------------------------------------------
// tf32 warp-MMA GEMM
// MODE 0: A = X (cvt to tf32), W = W1 [128,128]  -> g_h
// MODE 1: A = g_agg2 (pre-rounded), W = [Wmu|Wls] -> out + bias
// ---------------------------------------------------------------------------
#define AS_STRIDE 36
#define BS_STRIDE 136

__device__ __forceinline__ void mma_tf32(float* c, const uint32_t* a, const uint32_t* b) {
    asm volatile(
        "mma.sync.aligned.m16n8k8.row.col.f32.tf32.tf32.f32 "
        "{%0,%1,%2,%3}, {%4,%5,%6,%7}, {%8,%9}, {%0,%1,%2,%3};"
        : "+f"(c[0]), "+f"(c[1]), "+f"(c[2]), "+f"(c[3])
        : "r"(a[0]), "r"(a[1]), "r"(a[2]), "r"(a[3]), "r"(b[0]), "r"(b[1]));
}

template <int MODE>
__device__ void gemm_body(const float* __restrict__ Ap,
                          const float* __restrict__ Wa, const float* __restrict__ Wb,
                          const float* __restrict__ bmu, const float* __restrict__ bls,
                          float* __restrict__ out, int nrows, int blk) {
    __shared__ float As[128 * AS_STRIDE];
    __shared__ float Bs[32 * BS_STRIDE];

    const int tid    = threadIdx.x;
    const int lane   = tid & 31;
    const int wid    = tid >> 5;
    const int warp_m = wid >> 2;
    const int warp_n = wid & 3;
    const int rbase  = blk * 128;
    const int gid    = lane >> 2;
    const int tig    = lane & 3;

    float acc[4][4][4];
#pragma unroll
    for (int mt = 0; mt < 4; mt++)
#pragma unroll
        for (int nt = 0; nt < 4; nt++)
#pragma unroll
            for (int q = 0; q < 4; q++) acc[mt][nt][q] = 0.f;

    for (int kc = 0; kc < 128; kc += 32) {
#pragma unroll
        for (int i = 0; i < 4; i++) {
            int f   = tid + i * 256;
            int row = f >> 3;
            int c4  = (f & 7) * 4;
            float4 v = make_float4(0.f, 0.f, 0.f, 0.f);
            if (rbase + row < nrows)
                v = *reinterpret_cast<const float4*>(&Ap[(size_t)(rbase + row) * C + kc + c4]);
            if (MODE == 0) {
                uint4 w;
                w.x = f2tf32(v.x); w.y = f2tf32(v.y); w.z = f2tf32(v.z); w.w = f2tf32(v.w);
                *reinterpret_cast<uint4*>(&As[row * AS_STRIDE + c4]) = w;
            } else {
                *reinterpret_cast<float4*>(&As[row * AS_STRIDE + c4]) = v;
            }
        }
#pragma unroll
        for (int i = 0; i < 4; i++) {
            int f  = tid + i * 256;
            int k  = f >> 5;
            int n4 = (f & 31) * 4;
            float4 v;
            if (MODE == 0) {
                v = *reinterpret_cast<const float4*>(&Wa[(kc + k) * 128 + n4]);
            } else {
                v = (n4 < 64)
                    ? *reinterpret_cast<const float4*>(&Wa[(kc + k) * 64 + n4])
                    : *reinterpret_cast<const float4*>(&Wb[(kc + k) * 64 + n4 - 64]);
            }
            uint4 w;
            w.x = f2tf32(v.x); w.y = f2tf32(v.y); w.z = f2tf32(v.z); w.w = f2tf32(v.w);
            *reinterpret_cast<uint4*>(&Bs[k * BS_STRIDE + n4]) = w;
        }
        __syncthreads();

#pragma unroll
        for (int kk = 0; kk < 4; kk++) {
            const int k0 = kk * 8;
            uint32_t a[4][4], b[4][2];
#pragma unroll
            for (int mt = 0; mt < 4; mt++) {
                const float* p = &As[(warp_m * 64 + mt * 16 + gid) * AS_STRIDE + k0 + tig];
                a[mt][0] = __float_as_uint(p[0]);
                a[mt][1] = __float_as_uint(p[8 * AS_STRIDE]);
                a[mt][2] = __float_as_uint(p[4]);
                a[mt][3] = __float_as_uint(p[8 * AS_STRIDE + 4]);
            }
#pragma unroll
            for (int nt = 0; nt < 4; nt++) {
                const float* p = &Bs[(k0 + tig) * BS_STRIDE + warp_n * 32 + nt * 8 + gid];
                b[nt][0] = __float_as_uint(p[0]);
                b[nt][1] = __float_as_uint(p[4 * BS_STRIDE]);
            }
#pragma unroll
            for (int mt = 0; mt < 4; mt++)
#pragma unroll
                for (int nt = 0; nt < 4; nt++)
                    mma_tf32(acc[mt][nt], a[mt], b[nt]);
        }
        __syncthreads();
    }

#pragma unroll
    for (int mt = 0; mt < 4; mt++) {
        const int r0 = rbase + warp_m * 64 + mt * 16 + gid;
#pragma unroll
        for (int nt = 0; nt < 4; nt++) {
            const int col = warp_n * 32 + nt * 8 + tig * 2;
            if (MODE == 0) {
                if (r0 < nrows)
                    *reinterpret_cast<float2*>(&g_h[(size_t)r0 * C + col]) =
                        make_float2(acc[mt][nt][0], acc[mt][nt][1]);
                if (r0 + 8 < nrows)
                    *reinterpret_cast<float2*>(&g_h[(size_t)(r0 + 8) * C + col]) =
                        make_float2(acc[mt][nt][2], acc[mt][nt][3]);
            } else {
                const bool is_mu = (col < 64);
                const int  jo    = is_mu ? col : col - 64;
                const float* bp  = is_mu ? bmu : bls;
                float* obase     = is_mu ? out : out + (size_t)NN * 64;
                float2 bv = *reinterpret_cast<const float2*>(&bp[jo]);
                if (r0 < nrows)
                    *reinterpret_cast<float2*>(&obase[(size_t)r0 * 64 + jo]) =
                        make_float2(acc[mt][nt][0] + bv.x, acc[mt][nt][1] + bv.y);
                if (r0 + 8 < nrows)
                    *reinterpret_cast<float2*>(&obase[(size_t)(r0 + 8) * 64 + jo]) =
                        make_float2(acc[mt][nt][2] + bv.x, acc[mt][nt][3] + bv.y);
            }
        }
    }
}

__global__ __launch_bounds__(256, 2)
void gemm1_kernel(const float* __restrict__ X, const float* __restrict__ W1, int nrows) {
    gemm_body<0>(X, W1, nullptr, nullptr, nullptr, nullptr, nrows, blockIdx.x);
}

// chunked final GEMM: block index offset by blkbase
__global__ __launch_bounds__(256, 2)
void gemm_final_kernel(const float* __restrict__ Wmu, const float* __restrict__ Wls,
                       const float* __restrict__ bmu, const float* __restrict__ bls,
                       float* __restrict__ out, int nrows, int blkbase) {
    gemm_body<1>(g_agg2, Wmu, Wls, bmu, bls, out, nrows, blockIdx.x + blkbase);
}

// ---------------------------------------------------------------------------
// CSR gather (fp32): one warp per node, lane owns 4 channels; 8-deep MLP batch.
// STAGE 0: H=g_h  -> bias/relu/normalize -> g_hn       (nbase=0, ncount=NN)
// STAGE 1: H=g_hn -> g_agg2 (tf32-rounded)             (chunked)
// ---------------------------------------------------------------------------
template <int STAGE>
__global__ __launch_bounds__(256)
void gather_kernel(const float* __restrict__ b1, int nbase, int ncount) {
    int nl = (blockIdx.x * blockDim.x + threadIdx.x) >> 5;
    int lane = threadIdx.x & 31;
    if (nl >= ncount) return;
    int node = nbase + nl;

    const float* __restrict__ H = (STAGE == 0) ? g_h : g_hn;
    const size_t cb = (size_t)lane * 4;
    const float dn = g_dinv[node];

    float4 hv = *reinterpret_cast<const float4*>(&H[(size_t)node * C + cb]);
    float cc = dn * dn;
    float4 acc = make_float4(hv.x * cc, hv.y * cc, hv.z * cc, hv.w * cc);

    int e   = g_off[node];
    int end = g_off[node + 1];

    for (; e + 8 <= end; e += 8) {
        int s[8]; float cf[8]; float4 v[8];
#pragma unroll
        for (int j = 0; j < 8; j++) s[j] = g_csrc[e + j];
#pragma unroll
        for (int j = 0; j < 8; j++) cf[j] = g_dinv[s[j]] * dn;
#pragma unroll
        for (int j = 0; j < 8; j++)
            v[j] = *reinterpret_cast<const float4*>(&H[(size_t)s[j] * C + cb]);
#pragma unroll
        for (int j = 0; j < 8; j++) {
            acc.x = fmaf(cf[j], v[j].x, acc.x);
            acc.y = fmaf(cf[j], v[j].y, acc.y);
            acc.z = fmaf(cf[j], v[j].z, acc.z);
            acc.w = fmaf(cf[j], v[j].w, acc.w);
        }
    }
    if (e + 4 <= end) {
        int s[4]; float cf[4]; float4 v[4];
#pragma unroll
        for (int j = 0; j < 4; j++) s[j] = g_csrc[e + j];
#pragma unroll
        for (int j = 0; j < 4; j++) cf[j] = g_dinv[s[j]] * dn;
#pragma unroll
        for (int j = 0; j < 4; j++)
            v[j] = *reinterpret_cast<const float4*>(&H[(size_t)s[j] * C + cb]);
#pragma unroll
        for (int j = 0; j < 4; j++) {
            acc.x = fmaf(cf[j], v[j].x, acc.x);
            acc.y = fmaf(cf[j], v[j].y, acc.y);
            acc.z = fmaf(cf[j], v[j].z, acc.z);
            acc.w = fmaf(cf[j], v[j].w, acc.w);
        }
        e += 4;
    }
    for (; e < end; e++) {
        int s = g_csrc[e];
        float c = g_dinv[s] * dn;
        float4 v = *reinterpret_cast<const float4*>(&H[(size_t)s * C + cb]);
        acc.x = fmaf(c, v.x, acc.x);
        acc.y = fmaf(c, v.y, acc.y);
        acc.z = fmaf(c, v.z, acc.z);
        acc.w = fmaf(c, v.w, acc.w);
    }

    if (STAGE == 0) {
        float4 bv = *reinterpret_cast<const float4*>(&b1[cb]);
        acc.x = fmaxf(acc.x + bv.x, 0.f);
        acc.y = fmaxf(acc.y + bv.y, 0.f);
        acc.z = fmaxf(acc.z + bv.z, 0.f);
        acc.w = fmaxf(acc.w + bv.w, 0.f);
        float ss = acc.x * acc.x + acc.y * acc.y + acc.z * acc.z + acc.w * acc.w;
#pragma unroll
        for (int off = 16; off > 0; off >>= 1)
            ss += __shfl_xor_sync(0xffffffffu, ss, off);
        float scale = 1.0f / fmaxf(sqrtf(ss), 1e-12f);
        acc.x *= scale; acc.y *= scale; acc.z *= scale; acc.w *= scale;
        *reinterpret_cast<float4*>(&g_hn[(size_t)node * C + cb]) = acc;
    } else {
        uint4 w;
        w.x = f2tf32(acc.x); w.y = f2tf32(acc.y);
        w.z = f2tf32(acc.z); w.w = f2tf32(acc.w);
        *reinterpret_cast<uint4*>(&g_agg2[(size_t)node * C + cb]) = w;
    }
}

// ---------------------------------------------------------------------------
extern "C" void kernel_launch(void* const* d_in, const int* in_sizes, int n_in,
                              void* d_out, int out_size) {
    const float* x   = (const float*)d_in[0];
    const int*   ei  = (const int*)  d_in[1];
    const float* W1  = (const float*)d_in[2];
    const float* b1  = (const float*)d_in[3];
    const float* Wmu = (const float*)d_in[4];
    const float* bmu = (const float*)d_in[5];
    const float* Wls = (const float*)d_in[6];
    const float* bls = (const float*)d_in[7];
    float* out = (float*)d_out;

    const int* src = ei;
    const int* dst = ei + NE;

    const int gather0_blocks = (NN * 32 + 255) / 256;  // 12500

    // One-time setup (first call is the non-captured correctness run)
    static cudaStream_t s2 = nullptr;
    static cudaEvent_t  evF = nullptr, evJ = nullptr, evT = nullptr;
    static cudaEvent_t  evC[NCHUNK] = {};
    static void* cnt_ptr = nullptr;
    if (s2 == nullptr) {
        cudaStreamCreateWithFlags(&s2, cudaStreamNonBlocking);
        cudaEventCreateWithFlags(&evF, cudaEventDisableTiming);
        cudaEventCreateWithFlags(&evJ, cudaEventDisableTiming);
        cudaEventCreateWithFlags(&evT, cudaEventDisableTiming);
        for (int c = 0; c < NCHUNK; c++)
            cudaEventCreateWithFlags(&evC[c], cudaEventDisableTiming);
        cudaGetSymbolAddress(&cnt_ptr, g_cnt);
    }

    // main stream: zero counts, then fork
    cudaMemsetAsync(cnt_ptr, 0, NN * sizeof(int), 0);
    cudaEventRecord(evF, 0);
    cudaStreamWaitEvent(s2, evF, 0);

    // side stream: CSR chain (count -> scan -> fill)
    count_kernel<<<EDGE4_BLOCKS, 256, 0, s2>>>(dst);
    scan1_kernel<<<NBLK_SCAN, SCAN_CHUNK, 0, s2>>>();
    scan3_kernel<<<NBLK_SCAN, SCAN_CHUNK, 0, s2>>>();
    fill_kernel<<<EDGE4_BLOCKS, 256, 0, s2>>>(src, dst);
    cudaEventRecord(evJ, s2);

    // main stream: GEMM1 runs concurrently with the CSR chain
    gemm1_kernel<<<GEMM_BLOCKS, 256>>>(x, W1, NN);

    // join, then gather0 (global dependency, cannot be chunked)
    cudaStreamWaitEvent(0, evJ, 0);
    gather_kernel<0><<<gather0_blocks, 256>>>(b1, 0, NN);

    // pipelined tail: gather1 chunk c (stream 0) -> gemm_final chunk c (s2)
    for (int c = 0; c < NCHUNK; c++) {
        const int nbase  = c * CHUNK_NODES;
        const int ncount = (c == NCHUNK - 1) ? (NN - nbase) : CHUNK_NODES;
        const int gblk   = (ncount * 32 + 255) / 256;
        gather_kernel<1><<<gblk, 256>>>(b1, nbase, ncount);
        cudaEventRecord(evC[c], 0);
        cudaStreamWaitEvent(s2, evC[c], 0);
        const int fbase = c * CHUNK_BLKS;
        const int fblk  = (c == NCHUNK - 1) ? (GEMM_BLOCKS - fbase) : CHUNK_BLKS;
        gemm_final_kernel<<<fblk, 256, 0, s2>>>(Wmu, Wls, bmu, bls, out, NN, fbase);
    }
    cudaEventRecord(evT, s2);
    cudaStreamWaitEvent(0, evT, 0);
}

// round 15
// speedup vs baseline: 1.1331x; 1.1331x over previous
#include <cuda_runtime.h>
#include <cstdint>

#define NN 100000
#define NE 1600000
#define C  128

#define GEMM_BLOCKS  ((NN + 127) / 128)       // 782
#define EDGE4_BLOCKS ((NE / 4 + 255) / 256)   // 1563

#define SCAN_CHUNK 1024
#define NBLK_SCAN ((NN + SCAN_CHUNK - 1) / SCAN_CHUNK)   // 98

// ---------------------------------------------------------------------------
// Scratch (device globals — no allocation allowed)
// ---------------------------------------------------------------------------
__device__ int   g_cnt [NN];
__device__ int   g_off [NN + 1];
__device__ int   g_bsum[SCAN_CHUNK];
__device__ __align__(16) int g_csrc[NE];
__device__ float g_dinv[NN];
__device__ float g_h   [(size_t)NN * C];   // x@W1 (fp32)
__device__ float g_hn  [(size_t)NN * C];   // normalized hidden (fp32)
__device__ float g_agg2[(size_t)NN * C];   // stage-2 aggregate (tf32-rounded fp32)

__device__ __forceinline__ uint32_t f2tf32(float f) {
    uint32_t r; asm("cvt.rna.tf32.f32 %0, %1;" : "=r"(r) : "f"(f)); return r;
}

// ---------------------------------------------------------------------------
// CSR build pieces (side stream, overlapped with GEMM1)
// ---------------------------------------------------------------------------
__global__ void count_kernel(const int* __restrict__ dst) {
    int t = blockIdx.x * blockDim.x + threadIdx.x;
    if (t < NE / 4) {
        int4 d = reinterpret_cast<const int4*>(dst)[t];
        atomicAdd(&g_cnt[d.x], 1);
        atomicAdd(&g_cnt[d.y], 1);
        atomicAdd(&g_cnt[d.z], 1);
        atomicAdd(&g_cnt[d.w], 1);
    }
}

__global__ __launch_bounds__(SCAN_CHUNK)
void scan1_kernel() {
    const int tid = threadIdx.x, lane = tid & 31, wid = tid >> 5;
    int i = blockIdx.x * SCAN_CHUNK + tid;
    int v = (i < NN) ? g_cnt[i] : 0;
    int x = v;
#pragma unroll
    for (int off = 1; off < 32; off <<= 1) {
        int y = __shfl_up_sync(0xffffffffu, x, off);
        if (lane >= off) x += y;
    }
    __shared__ int ws[32];
    if (lane == 31) ws[wid] = x;
    __syncthreads();
    if (wid == 0) {
        int s = ws[lane];
        int t = s;
#pragma unroll
        for (int off = 1; off < 32; off <<= 1) {
            int y = __shfl_up_sync(0xffffffffu, t, off);
            if (lane >= off) t += y;
        }
        ws[lane] = t - s;
        if (lane == 31) g_bsum[blockIdx.x] = t;
    }
    __syncthreads();
    if (i < NN) g_off[i] = (x - v) + ws[wid];
}

__global__ __launch_bounds__(SCAN_CHUNK)
void scan3_kernel() {
    __shared__ int sb[128];
    const int tid = threadIdx.x;
    if (tid < 128) sb[tid] = (tid < NBLK_SCAN) ? g_bsum[tid] : 0;
    __syncthreads();
#pragma unroll
    for (int off = 1; off < 128; off <<= 1) {
        int t = 0;
        if (tid < 128 && tid >= off) t = sb[tid - off];
        __syncthreads();
        if (tid < 128) sb[tid] += t;
        __syncthreads();
    }
    const int boff = sb[blockIdx.x] - g_bsum[blockIdx.x];
    int i = blockIdx.x * SCAN_CHUNK + tid;
    if (i < NN) {
        g_off[i] += boff;
        g_dinv[i] = rsqrtf((float)g_cnt[i] + 1.0f);
        g_cnt[i] = 0;
    }
    if (i == 0) g_off[NN] = NE;
}

__global__ void fill_kernel(const int* __restrict__ src, const int* __restrict__ dst) {
    int t = blockIdx.x * blockDim.x + threadIdx.x;
    if (t < NE / 4) {
        int4 s = reinterpret_cast<const int4*>(src)[t];
        int4 d = reinterpret_cast<const int4*>(dst)[t];
        int p;
        p = atomicAdd(&g_cnt[d.x], 1); g_csrc[g_off[d.x] + p] = s.x;
        p = atomicAdd(&g_cnt[d.y], 1); g_csrc[g_off[d.y] + p] = s.y;
        p = atomicAdd(&g_cnt[d.z], 1); g_csrc[g_off[d.z] + p] = s.z;
        p = atomicAdd(&g_cnt[d.w], 1); g_csrc[g_off[d.w] + p] = s.w;
    }
}

// ---------------------------------------------------------------------------
// tf32 warp-MMA GEMM
// MODE 0: A = X (cvt to tf32), W = W1 [128,128]  -> g_h
// MODE 1: A = g_agg2 (pre-rounded), W = [Wmu|Wls] -> out + bias
// ---------------------------------------------------------------------------
#define AS_STRIDE 36
#define BS_STRIDE 136

__device__ __forceinline__ void mma_tf32(float* c, const uint32_t* a, const uint32_t* b) {
    asm volatile(
        "mma.sync.aligned.m16n8k8.row.col.f32.tf32.tf32.f32 "
        "{%0,%1,%2,%3}, {%4,%5,%6,%7}, {%8,%9}, {%0,%1,%2,%3};"
        : "+f"(c[0]), "+f"(c[1]), "+f"(c[2]), "+f"(c[3])
        : "r"(a[0]), "r"(a[1]), "r"(a[2]), "r"(a[3]), "r"(b[0]), "r"(b[1]));
}

template <int MODE>
__device__ void gemm_body(const float* __restrict__ Ap,
                          const float* __restrict__ Wa, const float* __restrict__ Wb,
                          const float* __restrict__ bmu, const float* __restrict__ bls,
                          float* __restrict__ out, int nrows, int blk) {
    __shared__ float As[128 * AS_STRIDE];
    __shared__ float Bs[32 * BS_STRIDE];

    const int tid    = threadIdx.x;
    const int lane   = tid & 31;
    const int wid    = tid >> 5;
    const int warp_m = wid >> 2;
    const int warp_n = wid & 3;
    const int rbase  = blk * 128;
    const int gid    = lane >> 2;
    const int tig    = lane & 3;

    float acc[4][4][4];
#pragma unroll
    for (int mt = 0; mt < 4; mt++)
#pragma unroll
        for (int nt = 0; nt < 4; nt++)
#pragma unroll
            for (int q = 0; q < 4; q++) acc[mt][nt][q] = 0.f;

    for (int kc = 0; kc < 128; kc += 32) {
#pragma unroll
        for (int i = 0; i < 4; i++) {
            int f   = tid + i * 256;
            int row = f >> 3;
            int c4  = (f & 7) * 4;
            float4 v = make_float4(0.f, 0.f, 0.f, 0.f);
            if (rbase + row < nrows)
                v = *reinterpret_cast<const float4*>(&Ap[(size_t)(rbase + row) * C + kc + c4]);
            if (MODE == 0) {
                uint4 w;
                w.x = f2tf32(v.x); w.y = f2tf32(v.y); w.z = f2tf32(v.z); w.w = f2tf32(v.w);
                *reinterpret_cast<uint4*>(&As[row * AS_STRIDE + c4]) = w;
            } else {
                *reinterpret_cast<float4*>(&As[row * AS_STRIDE + c4]) = v;
            }
        }
#pragma unroll
        for (int i = 0; i < 4; i++) {
            int f  = tid + i * 256;
            int k  = f >> 5;
            int n4 = (f & 31) * 4;
            float4 v;
            if (MODE == 0) {
                v = *reinterpret_cast<const float4*>(&Wa[(kc + k) * 128 + n4]);
            } else {
                v = (n4 < 64)
                    ? *reinterpret_cast<const float4*>(&Wa[(kc + k) * 64 + n4])
                    : *reinterpret_cast<const float4*>(&Wb[(kc + k) * 64 + n4 - 64]);
            }
            uint4 w;
            w.x = f2tf32(v.x); w.y = f2tf32(v.y); w.z = f2tf32(v.z); w.w = f2tf32(v.w);
            *reinterpret_cast<uint4*>(&Bs[k * BS_STRIDE + n4]) = w;
        }
        __syncthreads();

#pragma unroll
        for (int kk = 0; kk < 4; kk++) {
            const int k0 = kk * 8;
            uint32_t a[4][4], b[4][2];
#pragma unroll
            for (int mt = 0; mt < 4; mt++) {
                const float* p = &As[(warp_m * 64 + mt * 16 + gid) * AS_STRIDE + k0 + tig];
                a[mt][0] = __float_as_uint(p[0]);
                a[mt][1] = __float_as_uint(p[8 * AS_STRIDE]);
                a[mt][2] = __float_as_uint(p[4]);
                a[mt][3] = __float_as_uint(p[8 * AS_STRIDE + 4]);
            }
#pragma unroll
            for (int nt = 0; nt < 4; nt++) {
                const float* p = &Bs[(k0 + tig) * BS_STRIDE + warp_n * 32 + nt * 8 + gid];
                b[nt][0] = __float_as_uint(p[0]);
                b[nt][1] = __float_as_uint(p[4 * BS_STRIDE]);
            }
#pragma unroll
            for (int mt = 0; mt < 4; mt++)
#pragma unroll
                for (int nt = 0; nt < 4; nt++)
                    mma_tf32(acc[mt][nt], a[mt], b[nt]);
        }
        __syncthreads();
    }

#pragma unroll
    for (int mt = 0; mt < 4; mt++) {
        const int r0 = rbase + warp_m * 64 + mt * 16 + gid;
#pragma unroll
        for (int nt = 0; nt < 4; nt++) {
            const int col = warp_n * 32 + nt * 8 + tig * 2;
            if (MODE == 0) {
                if (r0 < nrows)
                    *reinterpret_cast<float2*>(&g_h[(size_t)r0 * C + col]) =
                        make_float2(acc[mt][nt][0], acc[mt][nt][1]);
                if (r0 + 8 < nrows)
                    *reinterpret_cast<float2*>(&g_h[(size_t)(r0 + 8) * C + col]) =
                        make_float2(acc[mt][nt][2], acc[mt][nt][3]);
            } else {
                const bool is_mu = (col < 64);
                const int  jo    = is_mu ? col : col - 64;
                const float* bp  = is_mu ? bmu : bls;
                float* obase     = is_mu ? out : out + (size_t)NN * 64;
                float2 bv = *reinterpret_cast<const float2*>(&bp[jo]);
                if (r0 < nrows)
                    *reinterpret_cast<float2*>(&obase[(size_t)r0 * 64 + jo]) =
                        make_float2(acc[mt][nt][0] + bv.x, acc[mt][nt][1] + bv.y);
                if (r0 + 8 < nrows)
                    *reinterpret_cast<float2*>(&obase[(size_t)(r0 + 8) * 64 + jo]) =
                        make_float2(acc[mt][nt][2] + bv.x, acc[mt][nt][3] + bv.y);
            }
        }
    }
}

__global__ __launch_bounds__(256, 2)
void gemm1_kernel(const float* __restrict__ X, const float* __restrict__ W1, int nrows) {
    gemm_body<0>(X, W1, nullptr, nullptr, nullptr, nullptr, nrows, blockIdx.x);
}

__global__ __launch_bounds__(256, 2)
void gemm_final_kernel(const float* __restrict__ Wmu, const float* __restrict__ Wls,
                       const float* __restrict__ bmu, const float* __restrict__ bls,
                       float* __restrict__ out, int nrows) {
    gemm_body<1>(g_agg2, Wmu, Wls, bmu, bls, out, nrows, blockIdx.x);
}

// ---------------------------------------------------------------------------
// CSR gather (fp32): one warp per node, lane owns 4 channels; 8-deep MLP batch
// with int4-vectorized index loads (g_csrc rows are contiguous per node).
// STAGE 0: H=g_h  -> bias/relu/normalize -> g_hn
// STAGE 1: H=g_hn -> g_agg2 (tf32-rounded)
// ---------------------------------------------------------------------------
template <int STAGE>
__global__ __launch_bounds__(256)
void gather_kernel(const float* __restrict__ b1) {
    int node = (blockIdx.x * blockDim.x + threadIdx.x) >> 5;
    int lane = threadIdx.x & 31;
    if (node >= NN) return;

    const float* __restrict__ H = (STAGE == 0) ? g_h : g_hn;
    const size_t cb = (size_t)lane * 4;
    const float dn = g_dinv[node];

    float4 hv = *reinterpret_cast<const float4*>(&H[(size_t)node * C + cb]);
    float cc = dn * dn;
    float4 acc = make_float4(hv.x * cc, hv.y * cc, hv.z * cc, hv.w * cc);

    int e   = g_off[node];
    int end = g_off[node + 1];

    // prolog: align e to 4 for int4 index loads
    while (e < end && (e & 3)) {
        int s = g_csrc[e];
        float c = g_dinv[s] * dn;
        float4 v = *reinterpret_cast<const float4*>(&H[(size_t)s * C + cb]);
        acc.x = fmaf(c, v.x, acc.x);
        acc.y = fmaf(c, v.y, acc.y);
        acc.z = fmaf(c, v.z, acc.z);
        acc.w = fmaf(c, v.w, acc.w);
        e++;
    }

    for (; e + 8 <= end; e += 8) {
        int4 sa = *reinterpret_cast<const int4*>(&g_csrc[e]);
        int4 sb = *reinterpret_cast<const int4*>(&g_csrc[e + 4]);
        int s[8] = {sa.x, sa.y, sa.z, sa.w, sb.x, sb.y, sb.z, sb.w};
        float cf[8]; float4 v[8];
#pragma unroll
        for (int j = 0; j < 8; j++) cf[j] = g_dinv[s[j]] * dn;
#pragma unroll
        for (int j = 0; j < 8; j++)
            v[j] = *reinterpret_cast<const float4*>(&H[(size_t)s[j] * C + cb]);
#pragma unroll
        for (int j = 0; j < 8; j++) {
            acc.x = fmaf(cf[j], v[j].x, acc.x);
            acc.y = fmaf(cf[j], v[j].y, acc.y);
            acc.z = fmaf(cf[j], v[j].z, acc.z);
            acc.w = fmaf(cf[j], v[j].w, acc.w);
        }
    }
    if (e + 4 <= end) {
        int4 sa = *reinterpret_cast<const int4*>(&g_csrc[e]);
        int s[4] = {sa.x, sa.y, sa.z, sa.w};
        float cf[4]; float4 v[4];
#pragma unroll
        for (int j = 0; j < 4; j++) cf[j] = g_dinv[s[j]] * dn;
#pragma unroll
        for (int j = 0; j < 4; j++)
            v[j] = *reinterpret_cast<const float4*>(&H[(size_t)s[j] * C + cb]);
#pragma unroll
        for (int j = 0; j < 4; j++) {
            acc.x = fmaf(cf[j], v[j].x, acc.x);
            acc.y = fmaf(cf[j], v[j].y, acc.y);
            acc.z = fmaf(cf[j], v[j].z, acc.z);
            acc.w = fmaf(cf[j], v[j].w, acc.w);
        }
        e += 4;
    }
    for (; e < end; e++) {
        int s = g_csrc[e];
        float c = g_dinv[s] * dn;
        float4 v = *reinterpret_cast<const float4*>(&H[(size_t)s * C + cb]);
        acc.x = fmaf(c, v.x, acc.x);
        acc.y = fmaf(c, v.y, acc.y);
        acc.z = fmaf(c, v.z, acc.z);
        acc.w = fmaf(c, v.w, acc.w);
    }

    if (STAGE == 0) {
        float4 bv = *reinterpret_cast<const float4*>(&b1[cb]);
        acc.x = fmaxf(acc.x + bv.x, 0.f);
        acc.y = fmaxf(acc.y + bv.y, 0.f);
        acc.z = fmaxf(acc.z + bv.z, 0.f);
        acc.w = fmaxf(acc.w + bv.w, 0.f);
        float ss = acc.x * acc.x + acc.y * acc.y + acc.z * acc.z + acc.w * acc.w;
#pragma unroll
        for (int off = 16; off > 0; off >>= 1)
            ss += __shfl_xor_sync(0xffffffffu, ss, off);
        float scale = 1.0f / fmaxf(sqrtf(ss), 1e-12f);
        acc.x *= scale; acc.y *= scale; acc.z *= scale; acc.w *= scale;
        *reinterpret_cast<float4*>(&g_hn[(size_t)node * C + cb]) = acc;
    } else {
        uint4 w;
        w.x = f2tf32(acc.x); w.y = f2tf32(acc.y);
        w.z = f2tf32(acc.z); w.w = f2tf32(acc.w);
        *reinterpret_cast<uint4*>(&g_agg2[(size_t)node * C + cb]) = w;
    }
}

// ---------------------------------------------------------------------------
extern "C" void kernel_launch(void* const* d_in, const int* in_sizes, int n_in,
                              void* d_out, int out_size) {
    const float* x   = (const float*)d_in[0];
    const int*   ei  = (const int*)  d_in[1];
    const float* W1  = (const float*)d_in[2];
    const float* b1  = (const float*)d_in[3];
    const float* Wmu = (const float*)d_in[4];
    const float* bmu = (const float*)d_in[5];
    const float* Wls = (const float*)d_in[6];
    const float* bls = (const float*)d_in[7];
    float* out = (float*)d_out;

    const int* src = ei;
    const int* dst = ei + NE;

    const int gather_blocks = (NN * 32 + 255) / 256;  // 12500

    // One-time setup (first call is the non-captured correctness run)
    static cudaStream_t s2 = nullptr;
    static cudaEvent_t  evF = nullptr, evJ = nullptr;
    static void* cnt_ptr = nullptr;
    if (s2 == nullptr) {
        cudaStreamCreateWithFlags(&s2, cudaStreamNonBlocking);
        cudaEventCreateWithFlags(&evF, cudaEventDisableTiming);
        cudaEventCreateWithFlags(&evJ, cudaEventDisableTiming);
        cudaGetSymbolAddress(&cnt_ptr, g_cnt);
    }

    // main stream: zero counts, then fork
    cudaMemsetAsync(cnt_ptr, 0, NN * sizeof(int), 0);
    cudaEventRecord(evF, 0);
    cudaStreamWaitEvent(s2, evF, 0);

    // side stream: CSR chain (count -> scan -> fill)
    count_kernel<<<EDGE4_BLOCKS, 256, 0, s2>>>(dst);
    scan1_kernel<<<NBLK_SCAN, SCAN_CHUNK, 0, s2>>>();
    scan3_kernel<<<NBLK_SCAN, SCAN_CHUNK, 0, s2>>>();
    fill_kernel<<<EDGE4_BLOCKS, 256, 0, s2>>>(src, dst);
    cudaEventRecord(evJ, s2);

    // main stream: GEMM1 runs concurrently with the CSR chain
    gemm1_kernel<<<GEMM_BLOCKS, 256>>>(x, W1, NN);

    // join, then the serial tail
    cudaStreamWaitEvent(0, evJ, 0);
    gather_kernel<0><<<gather_blocks, 256>>>(b1);
    gather_kernel<1><<<gather_blocks, 256>>>(b1);
    gemm_final_kernel<<<GEMM_BLOCKS, 256>>>(Wmu, Wls, bmu, bls, out, NN);
}

// round 16
// speedup vs baseline: 1.1774x; 1.0391x over previous
#include <cuda_runtime.h>
#include <cstdint>

#define NN 100000
#define NE 1600000
#define C  128

#define GEMM_BLOCKS  ((NN + 127) / 128)       // 782
#define EDGE4_BLOCKS ((NE / 4 + 255) / 256)   // 1563

#define SCAN_CHUNK 1024
#define NBLK_SCAN ((NN + SCAN_CHUNK - 1) / SCAN_CHUNK)   // 98

// ---------------------------------------------------------------------------
// Scratch (device globals — no allocation allowed)
// ---------------------------------------------------------------------------
__device__ int   g_cnt [NN];
__device__ int   g_off [NN + 1];
__device__ int   g_bsum[SCAN_CHUNK];
__device__ int   g_csrc[NE];
__device__ float g_dinv[NN];
__device__ float g_h   [(size_t)NN * C];   // x@W1 (fp32)
__device__ float g_hn  [(size_t)NN * C];   // dinv-prescaled normalized hidden
__device__ float g_agg2[(size_t)NN * C];   // stage-2 aggregate (tf32-rounded fp32)

__device__ __forceinline__ uint32_t f2tf32(float f) {
    uint32_t r; asm("cvt.rna.tf32.f32 %0, %1;" : "=r"(r) : "f"(f)); return r;
}

// ---------------------------------------------------------------------------
// CSR build pieces (side stream, overlapped with GEMM1)
// ---------------------------------------------------------------------------
__global__ void count_kernel(const int* __restrict__ dst) {
    int t = blockIdx.x * blockDim.x + threadIdx.x;
    if (t < NE / 4) {
        int4 d = reinterpret_cast<const int4*>(dst)[t];
        atomicAdd(&g_cnt[d.x], 1);
        atomicAdd(&g_cnt[d.y], 1);
        atomicAdd(&g_cnt[d.z], 1);
        atomicAdd(&g_cnt[d.w], 1);
    }
}

__global__ __launch_bounds__(SCAN_CHUNK)
void scan1_kernel() {
    const int tid = threadIdx.x, lane = tid & 31, wid = tid >> 5;
    int i = blockIdx.x * SCAN_CHUNK + tid;
    int v = (i < NN) ? g_cnt[i] : 0;
    int x = v;
#pragma unroll
    for (int off = 1; off < 32; off <<= 1) {
        int y = __shfl_up_sync(0xffffffffu, x, off);
        if (lane >= off) x += y;
    }
    __shared__ int ws[32];
    if (lane == 31) ws[wid] = x;
    __syncthreads();
    if (wid == 0) {
        int s = ws[lane];
        int t = s;
#pragma unroll
        for (int off = 1; off < 32; off <<= 1) {
            int y = __shfl_up_sync(0xffffffffu, t, off);
            if (lane >= off) t += y;
        }
        ws[lane] = t - s;
        if (lane == 31) g_bsum[blockIdx.x] = t;
    }
    __syncthreads();
    if (i < NN) g_off[i] = (x - v) + ws[wid];
}

__global__ __launch_bounds__(SCAN_CHUNK)
void scan3_kernel() {
    __shared__ int sb[128];
    const int tid = threadIdx.x;
    if (tid < 128) sb[tid] = (tid < NBLK_SCAN) ? g_bsum[tid] : 0;
    __syncthreads();
#pragma unroll
    for (int off = 1; off < 128; off <<= 1) {
        int t = 0;
        if (tid < 128 && tid >= off) t = sb[tid - off];
        __syncthreads();
        if (tid < 128) sb[tid] += t;
        __syncthreads();
    }
    const int boff = sb[blockIdx.x] - g_bsum[blockIdx.x];
    int i = blockIdx.x * SCAN_CHUNK + tid;
    if (i < NN) {
        g_off[i] += boff;
        g_dinv[i] = rsqrtf((float)g_cnt[i] + 1.0f);
        g_cnt[i] = 0;
    }
    if (i == 0) g_off[NN] = NE;
}

__global__ void fill_kernel(const int* __restrict__ src, const int* __restrict__ dst) {
    int t = blockIdx.x * blockDim.x + threadIdx.x;
    if (t < NE / 4) {
        int4 s = reinterpret_cast<const int4*>(src)[t];
        int4 d = reinterpret_cast<const int4*>(dst)[t];
        int p;
        p = atomicAdd(&g_cnt[d.x], 1); g_csrc[g_off[d.x] + p] = s.x;
        p = atomicAdd(&g_cnt[d.y], 1); g_csrc[g_off[d.y] + p] = s.y;
        p = atomicAdd(&g_cnt[d.z], 1); g_csrc[g_off[d.z] + p] = s.z;
        p = atomicAdd(&g_cnt[d.w], 1); g_csrc[g_off[d.w] + p] = s.w;
    }
}

// ---------------------------------------------------------------------------
// tf32 warp-MMA GEMM
// MODE 0: A = X (cvt to tf32), W = W1 [128,128]  -> g_h
// MODE 1: A = g_agg2 (pre-rounded), W = [Wmu|Wls] -> out + bias
// ---------------------------------------------------------------------------
#define AS_STRIDE 36
#define BS_STRIDE 136

__device__ __forceinline__ void mma_tf32(float* c, const uint32_t* a, const uint32_t* b) {
    asm volatile(
        "mma.sync.aligned.m16n8k8.row.col.f32.tf32.tf32.f32 "
        "{%0,%1,%2,%3}, {%4,%5,%6,%7}, {%8,%9}, {%0,%1,%2,%3};"
        : "+f"(c[0]), "+f"(c[1]), "+f"(c[2]), "+f"(c[3])
        : "r"(a[0]), "r"(a[1]), "r"(a[2]), "r"(a[3]), "r"(b[0]), "r"(b[1]));
}

template <int MODE>
__device__ void gemm_body(const float* __restrict__ Ap,
                          const float* __restrict__ Wa, const float* __restrict__ Wb,
                          const float* __restrict__ bmu, const float* __restrict__ bls,
                          float* __restrict__ out, int nrows, int blk) {
    __shared__ float As[128 * AS_STRIDE];
    __shared__ float Bs[32 * BS_STRIDE];

    const int tid    = threadIdx.x;
    const int lane   = tid & 31;
    const int wid    = tid >> 5;
    const int warp_m = wid >> 2;
    const int warp_n = wid & 3;
    const int rbase  = blk * 128;
    const int gid    = lane >> 2;
    const int tig    = lane & 3;

    float acc[4][4][4];
#pragma unroll
    for (int mt = 0; mt < 4; mt++)
#pragma unroll
        for (int nt = 0; nt < 4; nt++)
#pragma unroll
            for (int q = 0; q < 4; q++) acc[mt][nt][q] = 0.f;

    for (int kc = 0; kc < 128; kc += 32) {
#pragma unroll
        for (int i = 0; i < 4; i++) {
            int f   = tid + i * 256;
            int row = f >> 3;
            int c4  = (f & 7) * 4;
            float4 v = make_float4(0.f, 0.f, 0.f, 0.f);
            if (rbase + row < nrows)
                v = *reinterpret_cast<const float4*>(&Ap[(size_t)(rbase + row) * C + kc + c4]);
            if (MODE == 0) {
                uint4 w;
                w.x = f2tf32(v.x); w.y = f2tf32(v.y); w.z = f2tf32(v.z); w.w = f2tf32(v.w);
                *reinterpret_cast<uint4*>(&As[row * AS_STRIDE + c4]) = w;
            } else {
                *reinterpret_cast<float4*>(&As[row * AS_STRIDE + c4]) = v;
            }
        }
#pragma unroll
        for (int i = 0; i < 4; i++) {
            int f  = tid + i * 256;
            int k  = f >> 5;
            int n4 = (f & 31) * 4;
            float4 v;
            if (MODE == 0) {
                v = *reinterpret_cast<const float4*>(&Wa[(kc + k) * 128 + n4]);
            } else {
                v = (n4 < 64)
                    ? *reinterpret_cast<const float4*>(&Wa[(kc + k) * 64 + n4])
                    : *reinterpret_cast<const float4*>(&Wb[(kc + k) * 64 + n4 - 64]);
            }
            uint4 w;
            w.x = f2tf32(v.x); w.y = f2tf32(v.y); w.z = f2tf32(v.z); w.w = f2tf32(v.w);
            *reinterpret_cast<uint4*>(&Bs[k * BS_STRIDE + n4]) = w;
        }
        __syncthreads();

#pragma unroll
        for (int kk = 0; kk < 4; kk++) {
            const int k0 = kk * 8;
            uint32_t a[4][4], b[4][2];
#pragma unroll
            for (int mt = 0; mt < 4; mt++) {
                const float* p = &As[(warp_m * 64 + mt * 16 + gid) * AS_STRIDE + k0 + tig];
                a[mt][0] = __float_as_uint(p[0]);
                a[mt][1] = __float_as_uint(p[8 * AS_STRIDE]);
                a[mt][2] = __float_as_uint(p[4]);
                a[mt][3] = __float_as_uint(p[8 * AS_STRIDE + 4]);
            }
#pragma unroll
            for (int nt = 0; nt < 4; nt++) {
                const float* p = &Bs[(k0 + tig) * BS_STRIDE + warp_n * 32 + nt * 8 + gid];
                b[nt][0] = __float_as_uint(p[0]);
                b[nt][1] = __float_as_uint(p[4 * BS_STRIDE]);
            }
#pragma unroll
            for (int mt = 0; mt < 4; mt++)
#pragma unroll
                for (int nt = 0; nt < 4; nt++)
                    mma_tf32(acc[mt][nt], a[mt], b[nt]);
        }
        __syncthreads();
    }

#pragma unroll
    for (int mt = 0; mt < 4; mt++) {
        const int r0 = rbase + warp_m * 64 + mt * 16 + gid;
#pragma unroll
        for (int nt = 0; nt < 4; nt++) {
            const int col = warp_n * 32 + nt * 8 + tig * 2;
            if (MODE == 0) {
                if (r0 < nrows)
                    *reinterpret_cast<float2*>(&g_h[(size_t)r0 * C + col]) =
                        make_float2(acc[mt][nt][0], acc[mt][nt][1]);
                if (r0 + 8 < nrows)
                    *reinterpret_cast<float2*>(&g_h[(size_t)(r0 + 8) * C + col]) =
                        make_float2(acc[mt][nt][2], acc[mt][nt][3]);
            } else {
                const bool is_mu = (col < 64);
                const int  jo    = is_mu ? col : col - 64;
                const float* bp  = is_mu ? bmu : bls;
                float* obase     = is_mu ? out : out + (size_t)NN * 64;
                float2 bv = *reinterpret_cast<const float2*>(&bp[jo]);
                if (r0 < nrows)
                    *reinterpret_cast<float2*>(&obase[(size_t)r0 * 64 + jo]) =
                        make_float2(acc[mt][nt][0] + bv.x, acc[mt][nt][1] + bv.y);
                if (r0 + 8 < nrows)
                    *reinterpret_cast<float2*>(&obase[(size_t)(r0 + 8) * 64 + jo]) =
                        make_float2(acc[mt][nt][2] + bv.x, acc[mt][nt][3] + bv.y);
            }
        }
    }
}

__global__ __launch_bounds__(256, 2)
void gemm1_kernel(const float* __restrict__ X, const float* __restrict__ W1, int nrows) {
    gemm_body<0>(X, W1, nullptr, nullptr, nullptr, nullptr, nrows, blockIdx.x);
}

__global__ __launch_bounds__(256, 2)
void gemm_final_kernel(const float* __restrict__ Wmu, const float* __restrict__ Wls,
                       const float* __restrict__ bmu, const float* __restrict__ bls,
                       float* __restrict__ out, int nrows) {
    gemm_body<1>(g_agg2, Wmu, Wls, bmu, bls, out, nrows, blockIdx.x);
}

// ---------------------------------------------------------------------------
// CSR gather (fp32): one warp per node, lane owns 4 channels; 8-deep MLP batch.
// STAGE 0: H=g_h; per-edge coef dinv[s]*dn. Epilogue: bias/relu/normalize,
//          then PRESCALE by dn -> g_hn holds hn*dinv.
// STAGE 1: H=g_hn (prescaled). acc = dn * (Σ H[src] + H[node]) -> g_agg2 (tf32).
// ---------------------------------------------------------------------------
template <int STAGE>
__global__ __launch_bounds__(256)
void gather_kernel(const float* __restrict__ b1) {
    int node = (blockIdx.x * blockDim.x + threadIdx.x) >> 5;
    int lane = threadIdx.x & 31;
    if (node >= NN) return;

    const float* __restrict__ H = (STAGE == 0) ? g_h : g_hn;
    const size_t cb = (size_t)lane * 4;
    const float dn = g_dinv[node];

    float4 hv = *reinterpret_cast<const float4*>(&H[(size_t)node * C + cb]);
    float4 acc;
    if (STAGE == 0) {
        float cc = dn * dn;
        acc = make_float4(hv.x * cc, hv.y * cc, hv.z * cc, hv.w * cc);
    } else {
        acc = hv;   // prescaled: self term is just H[node]; final *dn at end
    }

    int e   = g_off[node];
    int end = g_off[node + 1];

    for (; e + 8 <= end; e += 8) {
        int s[8]; float4 v[8];
#pragma unroll
        for (int j = 0; j < 8; j++) s[j] = g_csrc[e + j];
        float cf[8];
        if (STAGE == 0) {
#pragma unroll
            for (int j = 0; j < 8; j++) cf[j] = g_dinv[s[j]] * dn;
        }
#pragma unroll
        for (int j = 0; j < 8; j++)
            v[j] = *reinterpret_cast<const float4*>(&H[(size_t)s[j] * C + cb]);
#pragma unroll
        for (int j = 0; j < 8; j++) {
            if (STAGE == 0) {
                acc.x = fmaf(cf[j], v[j].x, acc.x);
                acc.y = fmaf(cf[j], v[j].y, acc.y);
                acc.z = fmaf(cf[j], v[j].z, acc.z);
                acc.w = fmaf(cf[j], v[j].w, acc.w);
            } else {
                acc.x += v[j].x; acc.y += v[j].y;
                acc.z += v[j].z; acc.w += v[j].w;
            }
        }
    }
    if (e + 4 <= end) {
        int s[4]; float4 v[4];
#pragma unroll
        for (int j = 0; j < 4; j++) s[j] = g_csrc[e + j];
        float cf[4];
        if (STAGE == 0) {
#pragma unroll
            for (int j = 0; j < 4; j++) cf[j] = g_dinv[s[j]] * dn;
        }
#pragma unroll
        for (int j = 0; j < 4; j++)
            v[j] = *reinterpret_cast<const float4*>(&H[(size_t)s[j] * C + cb]);
#pragma unroll
        for (int j = 0; j < 4; j++) {
            if (STAGE == 0) {
                acc.x = fmaf(cf[j], v[j].x, acc.x);
                acc.y = fmaf(cf[j], v[j].y, acc.y);
                acc.z = fmaf(cf[j], v[j].z, acc.z);
                acc.w = fmaf(cf[j], v[j].w, acc.w);
            } else {
                acc.x += v[j].x; acc.y += v[j].y;
                acc.z += v[j].z; acc.w += v[j].w;
            }
        }
        e += 4;
    }
    for (; e < end; e++) {
        int s = g_csrc[e];
        float4 v = *reinterpret_cast<const float4*>(&H[(size_t)s * C + cb]);
        if (STAGE == 0) {
            float c = g_dinv[s] * dn;
            acc.x = fmaf(c, v.x, acc.x);
            acc.y = fmaf(c, v.y, acc.y);
            acc.z = fmaf(c, v.z, acc.z);
            acc.w = fmaf(c, v.w, acc.w);
        } else {
            acc.x += v.x; acc.y += v.y; acc.z += v.z; acc.w += v.w;
        }
    }

    if (STAGE == 0) {
        float4 bv = *reinterpret_cast<const float4*>(&b1[cb]);
        acc.x = fmaxf(acc.x + bv.x, 0.f);
        acc.y = fmaxf(acc.y + bv.y, 0.f);
        acc.z = fmaxf(acc.z + bv.z, 0.f);
        acc.w = fmaxf(acc.w + bv.w, 0.f);
        float ss = acc.x * acc.x + acc.y * acc.y + acc.z * acc.z + acc.w * acc.w;
#pragma unroll
        for (int off = 16; off > 0; off >>= 1)
            ss += __shfl_xor_sync(0xffffffffu, ss, off);
        float scale = dn / fmaxf(sqrtf(ss), 1e-12f);   // normalize AND prescale by dinv
        acc.x *= scale; acc.y *= scale; acc.z *= scale; acc.w *= scale;
        *reinterpret_cast<float4*>(&g_hn[(size_t)node * C + cb]) = acc;
    } else {
        uint4 w;
        w.x = f2tf32(acc.x * dn); w.y = f2tf32(acc.y * dn);
        w.z = f2tf32(acc.z * dn); w.w = f2tf32(acc.w * dn);
        *reinterpret_cast<uint4*>(&g_agg2[(size_t)node * C + cb]) = w;
    }
}

// ---------------------------------------------------------------------------
extern "C" void kernel_launch(void* const* d_in, const int* in_sizes, int n_in,
                              void* d_out, int out_size) {
    const float* x   = (const float*)d_in[0];
    const int*   ei  = (const int*)  d_in[1];
    const float* W1  = (const float*)d_in[2];
    const float* b1  = (const float*)d_in[3];
    const float* Wmu = (const float*)d_in[4];
    const float* bmu = (const float*)d_in[5];
    const float* Wls = (const float*)d_in[6];
    const float* bls = (const float*)d_in[7];
    float* out = (float*)d_out;

    const int* src = ei;
    const int* dst = ei + NE;

    const int gather_blocks = (NN * 32 + 255) / 256;  // 12500

    // One-time setup (first call is the non-captured correctness run)
    static cudaStream_t s2 = nullptr;
    static cudaEvent_t  evF = nullptr, evJ = nullptr;
    static void* cnt_ptr = nullptr;
    if (s2 == nullptr) {
        cudaStreamCreateWithFlags(&s2, cudaStreamNonBlocking);
        cudaEventCreateWithFlags(&evF, cudaEventDisableTiming);
        cudaEventCreateWithFlags(&evJ, cudaEventDisableTiming);
        cudaGetSymbolAddress(&cnt_ptr, g_cnt);
    }

    // main stream: zero counts, then fork
    cudaMemsetAsync(cnt_ptr, 0, NN * sizeof(int), 0);
    cudaEventRecord(evF, 0);
    cudaStreamWaitEvent(s2, evF, 0);

    // side stream: CSR chain (count -> scan -> fill)
    count_kernel<<<EDGE4_BLOCKS, 256, 0, s2>>>(dst);
    scan1_kernel<<<NBLK_SCAN, SCAN_CHUNK, 0, s2>>>();
    scan3_kernel<<<NBLK_SCAN, SCAN_CHUNK, 0, s2>>>();
    fill_kernel<<<EDGE4_BLOCKS, 256, 0, s2>>>(src, dst);
    cudaEventRecord(evJ, s2);

    // main stream: GEMM1 runs concurrently with the CSR chain
    gemm1_kernel<<<GEMM_BLOCKS, 256>>>(x, W1, NN);

    // join, then the serial tail
    cudaStreamWaitEvent(0, evJ, 0);
    gather_kernel<0><<<gather_blocks, 256>>>(b1);
    gather_kernel<1><<<gather_blocks, 256>>>(b1);
    gemm_final_kernel<<<GEMM_BLOCKS, 256>>>(Wmu, Wls, bmu, bls, out, NN);
}